// round 1
// baseline (speedup 1.0000x reference)
#include <cuda_runtime.h>
#include <math.h>

// GaussianSQuantizer: fused fp32 GEMM + online softmax stats + argmax gather.
// out = [z_quantized (n*128 floats), loss_kld_reg, loss_commit]

#define EDIM 128
#define BM 128
#define BN 128
#define NTHREADS 256
#define F_LOG2PI 1.8378770664093453f

#define MAX_N 65536
#define MAX_NE 4096
#define MAX_BLOCKS (MAX_N / BM)

__device__ float g_z2[MAX_N];
__device__ float g_e2[MAX_NE];
__device__ float g_scal[2];             // [0] = 1/v, [1] = 0.5 * EDIM * (log v + LOG2PI)
__device__ float g_part[MAX_BLOCKS][2]; // per-block partial (kld_sum, commit_sum)

// ---------------------------------------------------------------------------
// Prep: row sums of squares for z and embedding, plus the variance scalars.
// ---------------------------------------------------------------------------
__global__ void gsq_prep_kernel(const float* __restrict__ z,
                                const float* __restrict__ emb,
                                const float* __restrict__ var_q_logit,
                                const float* __restrict__ var_init,
                                int n, int ne) {
    int t = blockIdx.x * blockDim.x + threadIdx.x;
    if (t == 0) {
        float lg = var_q_logit[0];
        float v = (1.0f / (1.0f + expf(-lg))) * 2.0f * var_init[0];
        g_scal[0] = 1.0f / v;
        g_scal[1] = 0.5f * (float)EDIM * (logf(v) + F_LOG2PI);
    }
    if (t < n) {
        const float4* p = (const float4*)(z + (size_t)t * EDIM);
        float s = 0.0f;
        #pragma unroll
        for (int i = 0; i < EDIM / 4; i++) {
            float4 v4 = p[i];
            s += v4.x * v4.x + v4.y * v4.y + v4.z * v4.z + v4.w * v4.w;
        }
        g_z2[t] = s;
    } else if (t < n + ne) {
        int k = t - n;
        const float4* p = (const float4*)(emb + (size_t)k * EDIM);
        float s = 0.0f;
        #pragma unroll
        for (int i = 0; i < EDIM / 4; i++) {
            float4 v4 = p[i];
            s += v4.x * v4.x + v4.y * v4.y + v4.z * v4.z + v4.w * v4.w;
        }
        g_e2[k] = s;
    }
}

// ---------------------------------------------------------------------------
// Main: each block owns BM=128 rows; loops over the codebook in BN=128 tiles.
// Per tile: 128x128x128 fp32 GEMM (register-tiled 8x8/thread), then online
// softmax-stat update per row (max, argmax, sum e^a, sum a*e^a).
// ---------------------------------------------------------------------------
__global__ __launch_bounds__(NTHREADS, 1)
void gsq_main_kernel(const float* __restrict__ z,
                     const float* __restrict__ emb,
                     float* __restrict__ out,
                     int n, int ne) {
    extern __shared__ float sm[];
    float* Zs = sm;                 // [EDIM][BM] transposed  (d-major)
    float* Es = sm + EDIM * BM;     // [EDIM][BN] transposed; reused as S [BM][BN]

    __shared__ float z2s[BM];
    __shared__ float e2s[BN];
    __shared__ float rm[BM], rl[BM], rt[BM], rbv[BM];
    __shared__ int   rbi[BM];
    __shared__ float redk[BM], redc[BM];

    const int tid = threadIdx.x;
    const int block_row = blockIdx.x * BM;

    // ---- load Z tile, transposed into Zs[d][m] (STS conflict-free: lanes = m)
    {
        int m = tid & 127;
        int dq0 = tid >> 7;
        const float* zg = z + (size_t)(block_row + m) * EDIM;
        #pragma unroll
        for (int i = 0; i < 16; i++) {
            int dq = dq0 + 2 * i;
            float4 v = *(const float4*)(zg + dq * 4);
            Zs[(dq * 4 + 0) * BM + m] = v.x;
            Zs[(dq * 4 + 1) * BM + m] = v.y;
            Zs[(dq * 4 + 2) * BM + m] = v.z;
            Zs[(dq * 4 + 3) * BM + m] = v.w;
        }
    }
    if (tid < BM) {
        z2s[tid] = g_z2[block_row + tid];
        rm[tid]  = -INFINITY;
        rl[tid]  = 0.0f;
        rt[tid]  = 0.0f;
        rbv[tid] = -INFINITY;
        rbi[tid] = 0;
    }

    const float inv_v = g_scal[0];
    const float halfC = g_scal[1];

    const int tx = tid & 15;       // 0..15  -> columns
    const int ty = tid >> 4;       // 0..15  -> rows
    const int r0 = ty * 8;
    const int c0 = tx * 8;

    const int ntiles = ne / BN;
    for (int kt = 0; kt < ntiles; kt++) {
        __syncthreads();   // previous epilogue done with Es/S

        // ---- load E tile transposed into Es[d][k]
        {
            int m = tid & 127;
            int dq0 = tid >> 7;
            const float* eg = emb + (size_t)(kt * BN + m) * EDIM;
            #pragma unroll
            for (int i = 0; i < 16; i++) {
                int dq = dq0 + 2 * i;
                float4 v = *(const float4*)(eg + dq * 4);
                Es[(dq * 4 + 0) * BM + m] = v.x;
                Es[(dq * 4 + 1) * BM + m] = v.y;
                Es[(dq * 4 + 2) * BM + m] = v.z;
                Es[(dq * 4 + 3) * BM + m] = v.w;
            }
            if (tid < BN) e2s[tid] = g_e2[kt * BN + tid];
        }
        __syncthreads();

        // ---- 128x128x128 GEMM, 8x8 per thread
        float acc[8][8];
        #pragma unroll
        for (int i = 0; i < 8; i++)
            #pragma unroll
            for (int j = 0; j < 8; j++) acc[i][j] = 0.0f;

        #pragma unroll 4
        for (int d = 0; d < EDIM; d++) {
            float4 za = *(const float4*)&Zs[d * BM + r0];
            float4 zb = *(const float4*)&Zs[d * BM + r0 + 4];
            float4 ea = *(const float4*)&Es[d * BM + c0];
            float4 eb = *(const float4*)&Es[d * BM + c0 + 4];
            float zr[8] = {za.x, za.y, za.z, za.w, zb.x, zb.y, zb.z, zb.w};
            float ec[8] = {ea.x, ea.y, ea.z, ea.w, eb.x, eb.y, eb.z, eb.w};
            #pragma unroll
            for (int i = 0; i < 8; i++)
                #pragma unroll
                for (int j = 0; j < 8; j++)
                    acc[i][j] = fmaf(zr[i], ec[j], acc[i][j]);
        }
        __syncthreads();   // everyone done reading Es

        // ---- bounce S (raw dot) through smem (reuse Es region as [BM][BN])
        float* S = Es;
        #pragma unroll
        for (int i = 0; i < 8; i++) {
            float4 lo = make_float4(acc[i][0], acc[i][1], acc[i][2], acc[i][3]);
            float4 hi = make_float4(acc[i][4], acc[i][5], acc[i][6], acc[i][7]);
            *(float4*)&S[(r0 + i) * BN + c0]     = lo;
            *(float4*)&S[(r0 + i) * BN + c0 + 4] = hi;
        }
        __syncthreads();

        // ---- online softmax update: 2 threads per row, 64 cols each
        {
            const int r = tid >> 1;
            const int h = tid & 1;
            const int cbase = h * 64;
            const float z2h = 0.5f * z2s[r];

            // pass 1: local max + argmax (first-index tie rule within half)
            float vmax = -INFINITY;
            int vidx = 0;
            #pragma unroll 8
            for (int c = 0; c < 64; c++) {
                int cc = cbase + c;
                float a = (S[r * BN + cc] - z2h - 0.5f * e2s[cc]) * inv_v;
                if (a > vmax) { vmax = a; vidx = kt * BN + cc; }
            }
            // pass 2: sums relative to local max
            float l = 0.0f, t = 0.0f;
            #pragma unroll 8
            for (int c = 0; c < 64; c++) {
                int cc = cbase + c;
                float a = (S[r * BN + cc] - z2h - 0.5f * e2s[cc]) * inv_v;
                float e = __expf(a - vmax);
                l += e;
                t += a * e;     // t = sum a * e^{a - vmax}
            }

            // merge the two halves via shuffle (partner = lane^1, same warp)
            float om  = __shfl_xor_sync(0xffffffffu, vmax, 1);
            float ol  = __shfl_xor_sync(0xffffffffu, l, 1);
            float ot  = __shfl_xor_sync(0xffffffffu, t, 1);
            int   obi = __shfl_xor_sync(0xffffffffu, vidx, 1);

            float mm  = fmaxf(vmax, om);
            float s1  = __expf(vmax - mm);
            float s2  = __expf(om - mm);
            float l12 = l * s1 + ol * s2;
            float t12 = t * s1 + ot * s2;
            float bv12 = vmax; int bi12 = vidx;
            if (om > bv12 || (om == bv12 && obi < bi12)) { bv12 = om; bi12 = obi; }

            if (h == 0) {
                float pm = rm[r];
                float nm = fmaxf(pm, mm);
                float sp = __expf(pm - nm);
                float sn = __expf(mm - nm);
                rl[r] = rl[r] * sp + l12 * sn;
                rt[r] = rt[r] * sp + t12 * sn;
                rm[r] = nm;
                if (bv12 > rbv[r] || (bv12 == rbv[r] && bi12 < rbi[r])) {
                    rbv[r] = bv12; rbi[r] = bi12;
                }
            }
        }
    }
    __syncthreads();

    // ---- per-row finals + block loss reduction
    if (tid < BM) {
        int r = tid;
        float palog = rt[r] / rl[r];                  // sum_k p_k * a_k
        float lse   = rm[r] + logf(rl[r]);
        redk[r] = palog - lse;                        // sum p*logp
        redc[r] = halfC - palog;                      // -(sum p*logit)
    }
    __syncthreads();
    for (int s = BM / 2; s > 0; s >>= 1) {
        if (tid < s) { redk[tid] += redk[tid + s]; redc[tid] += redc[tid + s]; }
        __syncthreads();
    }
    if (tid == 0) {
        g_part[blockIdx.x][0] = redk[0];
        g_part[blockIdx.x][1] = redc[0];
    }

    // ---- gather z_quantized = embedding[argmax]
    {
        const int r = tid >> 1;
        const int h = tid & 1;
        const int bi = rbi[r];
        const float4* src = (const float4*)(emb + (size_t)bi * EDIM) + h * 16;
        float4* dst = (float4*)(out + (size_t)(block_row + r) * EDIM) + h * 16;
        #pragma unroll
        for (int i = 0; i < 16; i++) dst[i] = src[i];
    }
}

// ---------------------------------------------------------------------------
// Finish: reduce per-block partials, write the two loss scalars.
// ---------------------------------------------------------------------------
__global__ void gsq_finish_kernel(float* __restrict__ out, int n, int nblocks) {
    __shared__ double sk[256], sc[256];
    int t = threadIdx.x;
    double a = 0.0, b = 0.0;
    for (int i = t; i < nblocks; i += 256) {
        a += (double)g_part[i][0];
        b += (double)g_part[i][1];
    }
    sk[t] = a; sc[t] = b;
    __syncthreads();
    for (int s = 128; s > 0; s >>= 1) {
        if (t < s) { sk[t] += sk[t + s]; sc[t] += sc[t + s]; }
        __syncthreads();
    }
    if (t == 0) {
        double dn = (double)n;
        out[(size_t)n * EDIM + 0] = (float)(sk[0] / dn);
        out[(size_t)n * EDIM + 1] = (float)(sc[0] / dn);
    }
}

// ---------------------------------------------------------------------------
extern "C" void kernel_launch(void* const* d_in, const int* in_sizes, int n_in,
                              void* d_out, int out_size) {
    const float* z   = (const float*)d_in[0];
    const float* emb = (const float*)d_in[1];
    const float* vql = (const float*)d_in[2];
    const float* vi  = (const float*)d_in[3];
    float* out = (float*)d_out;

    int n  = in_sizes[0] / EDIM;
    int ne = in_sizes[1] / EDIM;

    size_t smem_bytes = (size_t)(2 * EDIM * BM) * sizeof(float);   // 128 KB
    cudaFuncSetAttribute(gsq_main_kernel,
                         cudaFuncAttributeMaxDynamicSharedMemorySize,
                         (int)smem_bytes);

    int prep_threads = 256;
    int prep_blocks = (n + ne + prep_threads - 1) / prep_threads;
    gsq_prep_kernel<<<prep_blocks, prep_threads>>>(z, emb, vql, vi, n, ne);

    gsq_main_kernel<<<n / BM, NTHREADS, smem_bytes>>>(z, emb, out, n, ne);

    gsq_finish_kernel<<<1, 256>>>(out, n, n / BM);
}

// round 5
// speedup vs baseline: 1.7960x; 1.7960x over previous
#include <cuda_runtime.h>
#include <math.h>
#include <stdint.h>

#define EDIM 128
#define BM 128
#define BN 128
#define NTHREADS 256
#define F_LOG2PI 1.8378770664093453f

__device__ float g_z2[65536];
__device__ float g_e2[4096];
__device__ float g_scal[2];          // [0]=1/v  [1]=0.5*EDIM*(log v + LOG2PI)
__device__ float g_part[512][2];

// ---------------------------------------------------------------------------
__device__ __forceinline__ uint32_t smem_u32(const void* p) {
    uint32_t a;
    asm("{ .reg .u64 t; cvta.to.shared.u64 t, %1; cvt.u32.u64 %0, t; }" : "=r"(a) : "l"(p));
    return a;
}
__device__ __forceinline__ uint32_t tf32_rna(float x) {
    uint32_t r;
    asm("cvt.rna.tf32.f32 %0, %1;" : "=r"(r) : "f"(x));
    return r;
}

#define CPASYNC16(dst32, srcptr) \
    asm volatile("cp.async.cg.shared.global [%0], [%1], 16;" :: "r"(dst32), "l"(srcptr) : "memory")
#define CPCOMMIT() asm volatile("cp.async.commit_group;" ::: "memory")
#define CPWAIT1()  asm volatile("cp.async.wait_group 1;" ::: "memory")
#define CPWAIT0()  asm volatile("cp.async.wait_group 0;" ::: "memory")

#define MMA_TF32(c, a, b)                                                      \
    asm volatile("mma.sync.aligned.m16n8k8.row.col.f32.tf32.tf32.f32 "         \
        "{%0,%1,%2,%3},{%4,%5,%6,%7},{%8,%9},{%0,%1,%2,%3};"                   \
        : "+f"((c)[0]), "+f"((c)[1]), "+f"((c)[2]), "+f"((c)[3])               \
        : "r"((a)[0]), "r"((a)[1]), "r"((a)[2]), "r"((a)[3]),                  \
          "r"((b)[0]), "r"((b)[1]))

// byte offset of element (row, col) in a [128][128] fp32 tile with 16B-chunk
// XOR swizzle (conflict-free for all fragment access patterns below)
__device__ __forceinline__ int swoff(int row, int col) {
    return (row << 9) + ((((col >> 2) ^ (row & 15))) << 4) + ((col & 3) << 2);
}

// ---------------------------------------------------------------------------
__global__ void gsq_prep_kernel(const float* __restrict__ z,
                                const float* __restrict__ emb,
                                const float* __restrict__ var_q_logit,
                                const float* __restrict__ var_init,
                                int n, int ne) {
    int t = blockIdx.x * blockDim.x + threadIdx.x;
    if (t == 0) {
        float lg = var_q_logit[0];
        float v = (1.0f / (1.0f + expf(-lg))) * 2.0f * var_init[0];
        g_scal[0] = 1.0f / v;
        g_scal[1] = 0.5f * (float)EDIM * (logf(v) + F_LOG2PI);
    }
    if (t < n) {
        const float4* p = (const float4*)(z + (size_t)t * EDIM);
        float s = 0.0f;
        #pragma unroll
        for (int i = 0; i < EDIM / 4; i++) {
            float4 v4 = p[i];
            s += v4.x * v4.x + v4.y * v4.y + v4.z * v4.z + v4.w * v4.w;
        }
        g_z2[t] = s;
    } else if (t < n + ne) {
        int k = t - n;
        const float4* p = (const float4*)(emb + (size_t)k * EDIM);
        float s = 0.0f;
        #pragma unroll
        for (int i = 0; i < EDIM / 4; i++) {
            float4 v4 = p[i];
            s += v4.x * v4.x + v4.y * v4.y + v4.z * v4.z + v4.w * v4.w;
        }
        g_e2[k] = s;
    }
}

// ---------------------------------------------------------------------------
// Main: mma.sync tf32 3-split GEMM fused with online softmax + argmax.
// 8 warps = 4(M) x 2(N); warp tile 32x64; fp32 operands in SMEM, hi/lo tf32
// split done at fragment-load time.
// ---------------------------------------------------------------------------
__global__ __launch_bounds__(NTHREADS, 1)
void gsq_main_kernel(const float* __restrict__ z,
                     const float* __restrict__ emb,
                     float* __restrict__ out,
                     int n, int ne) {
    extern __shared__ char dynsm[];     // [0,64K) Z ; [64K,128K) E buf0 ; [128K,192K) E buf1
    __shared__ float e2v_s[4096];
    __shared__ float smm2[128][2], sml2[128][2], smt2[128][2], smbv2[128][2];
    __shared__ int   smbi2[128][2];
    __shared__ float redk[128], redc[128];
    __shared__ int   finbi[128];

    const int tid  = threadIdx.x;
    const int w    = tid >> 5;
    const int l    = tid & 31;
    const int wm   = w >> 1;            // 0..3  M band
    const int wn   = w & 1;             // 0..1  N half
    const int block_row = blockIdx.x * BM;

    char* zs = dynsm;
    const uint32_t zs32 = smem_u32(dynsm);
    const uint32_t eb32[2] = { zs32 + 65536u, zs32 + 131072u };

    const float inv_v = g_scal[0];
    const float halfC = g_scal[1];

    for (int i = tid; i < 4096; i += NTHREADS) e2v_s[i] = 0.5f * inv_v * g_e2[i];

    // per-thread row constants (s = mb*2+half -> row = wm*32 + mb*16 + l/4 + half*8)
    float c_r[4];
    #pragma unroll
    for (int s = 0; s < 4; s++) {
        int row = wm * 32 + (s >> 1) * 16 + (l >> 2) + (s & 1) * 8;
        c_r[s] = -0.5f * inv_v * g_z2[block_row + row];
    }

    // ---- prefetch Z (group), then E tile 0 (group)
    {
        const float* src = z + (size_t)block_row * EDIM;
        #pragma unroll
        for (int i = 0; i < 16; i++) {
            int u = i * NTHREADS + tid;
            int row = u >> 5, chunk = u & 31;
            int chk = chunk ^ (row & 15);
            CPASYNC16(zs32 + row * 512 + chk * 16, src + row * 128 + chunk * 4);
        }
        CPCOMMIT();
    }
    {
        const float* src = emb;
        #pragma unroll
        for (int i = 0; i < 16; i++) {
            int u = i * NTHREADS + tid;
            int row = u >> 5, chunk = u & 31;
            int chk = chunk ^ (row & 15);
            CPASYNC16(eb32[0] + row * 512 + chk * 16, src + row * 128 + chunk * 4);
        }
        CPCOMMIT();
    }

    // running per-row softmax state (4 rows per thread; quad-redundant)
    float rm_[4], rl_[4], rt_[4], rbv_[4];
    int rbi_[4];
    #pragma unroll
    for (int s = 0; s < 4; s++) { rm_[s] = -INFINITY; rl_[s] = 0.f; rt_[s] = 0.f; rbv_[s] = -INFINITY; rbi_[s] = 0; }

    const int ntiles = ne / BN;         // 32
    for (int t = 0; t < ntiles; t++) {
        // prefetch next E tile
        if (t + 1 < ntiles) {
            const float* src = emb + (size_t)(t + 1) * BN * EDIM;
            const uint32_t db = eb32[(t + 1) & 1];
            #pragma unroll
            for (int i = 0; i < 16; i++) {
                int u = i * NTHREADS + tid;
                int row = u >> 5, chunk = u & 31;
                int chk = chunk ^ (row & 15);
                CPASYNC16(db + row * 512 + chk * 16, src + row * 128 + chunk * 4);
            }
            CPCOMMIT();
            CPWAIT1();
        } else {
            CPWAIT0();
        }
        __syncthreads();

        char* es = dynsm + 65536 + (size_t)(t & 1) * 65536;

        // ---- GEMM: 3-split tf32, warp tile 32x64
        float acc[2][8][4];
        #pragma unroll
        for (int mb = 0; mb < 2; mb++)
            #pragma unroll
            for (int nb = 0; nb < 8; nb++)
                #pragma unroll
                for (int q = 0; q < 4; q++) acc[mb][nb][q] = 0.0f;

        #pragma unroll 4
        for (int kb = 0; kb < 16; kb++) {
            const int k0 = kb * 8 + (l & 3);
            uint32_t ah[2][4], al[2][4];
            #pragma unroll
            for (int mb = 0; mb < 2; mb++) {
                int r0 = wm * 32 + mb * 16 + (l >> 2);
                float v0 = *(const float*)(zs + swoff(r0,     k0));
                float v1 = *(const float*)(zs + swoff(r0 + 8, k0));
                float v2 = *(const float*)(zs + swoff(r0,     k0 + 4));
                float v3 = *(const float*)(zs + swoff(r0 + 8, k0 + 4));
                ah[mb][0] = tf32_rna(v0); al[mb][0] = __float_as_uint(v0 - __uint_as_float(ah[mb][0]));
                ah[mb][1] = tf32_rna(v1); al[mb][1] = __float_as_uint(v1 - __uint_as_float(ah[mb][1]));
                ah[mb][2] = tf32_rna(v2); al[mb][2] = __float_as_uint(v2 - __uint_as_float(ah[mb][2]));
                ah[mb][3] = tf32_rna(v3); al[mb][3] = __float_as_uint(v3 - __uint_as_float(ah[mb][3]));
            }
            uint32_t bh[8][2], bl[8][2];
            #pragma unroll
            for (int nb = 0; nb < 8; nb++) {
                int nr = wn * 64 + nb * 8 + (l >> 2);
                float w0 = *(const float*)(es + swoff(nr, k0));
                float w1 = *(const float*)(es + swoff(nr, k0 + 4));
                bh[nb][0] = tf32_rna(w0); bl[nb][0] = __float_as_uint(w0 - __uint_as_float(bh[nb][0]));
                bh[nb][1] = tf32_rna(w1); bl[nb][1] = __float_as_uint(w1 - __uint_as_float(bh[nb][1]));
            }
            #pragma unroll
            for (int mb = 0; mb < 2; mb++)
                #pragma unroll
                for (int nb = 0; nb < 8; nb++) {
                    MMA_TF32(acc[mb][nb], ah[mb], bh[nb]);   // hi*hi
                    MMA_TF32(acc[mb][nb], ah[mb], bl[nb]);   // hi*lo
                    MMA_TF32(acc[mb][nb], al[mb], bh[nb]);   // lo*hi
                }
        }

        // ---- fused epilogue: online softmax stats per row
        const int colq = (l & 3) * 2;                  // thread's col pair base
        #pragma unroll
        for (int mb = 0; mb < 2; mb++) {
            #pragma unroll
            for (int half = 0; half < 2; half++) {
                const int s = mb * 2 + half;
                float vals[16];
                int cb0 = t * BN + wn * 64;
                #pragma unroll
                for (int nb = 0; nb < 8; nb++) {
                    #pragma unroll
                    for (int j = 0; j < 2; j++) {
                        int col = cb0 + nb * 8 + colq + j;
                        vals[nb * 2 + j] =
                            fmaf(acc[mb][nb][half * 2 + j], inv_v, c_r[s]) - e2v_s[col];
                    }
                }
                // thread-local max + first-index argmax (cols ascending in nb,j)
                float vmax = vals[0];
                int vidx = cb0 + colq;
                #pragma unroll
                for (int q = 1; q < 16; q++) {
                    int col = cb0 + (q >> 1) * 8 + colq + (q & 1);
                    if (vals[q] > vmax) { vmax = vals[q]; vidx = col; }
                }
                // quad reduce (lanes sharing a row)
                #pragma unroll
                for (int off = 1; off < 4; off <<= 1) {
                    float ov = __shfl_xor_sync(0xffffffffu, vmax, off);
                    int   oi = __shfl_xor_sync(0xffffffffu, vidx, off);
                    if (ov > vmax || (ov == vmax && oi < vidx)) { vmax = ov; vidx = oi; }
                }
                // sums relative to row max
                float ls = 0.0f, ts = 0.0f;
                #pragma unroll
                for (int q = 0; q < 16; q++) {
                    float e = __expf(vals[q] - vmax);
                    ls += e;
                    ts = fmaf(vals[q], e, ts);
                }
                #pragma unroll
                for (int off = 1; off < 4; off <<= 1) {
                    ls += __shfl_xor_sync(0xffffffffu, ls, off);
                    ts += __shfl_xor_sync(0xffffffffu, ts, off);
                }
                // online merge
                float nm = fmaxf(rm_[s], vmax);
                float s1 = __expf(rm_[s] - nm), s2 = __expf(vmax - nm);
                rl_[s] = rl_[s] * s1 + ls * s2;
                rt_[s] = rt_[s] * s1 + ts * s2;
                rm_[s] = nm;
                if (vmax > rbv_[s]) { rbv_[s] = vmax; rbi_[s] = vidx; }
            }
        }
        __syncthreads();   // all warps done with E buffer before it's refilled
    }

    // ---- publish per-(row, wn) states
    if ((l & 3) == 0) {
        #pragma unroll
        for (int s = 0; s < 4; s++) {
            int row = wm * 32 + (s >> 1) * 16 + (l >> 2) + (s & 1) * 8;
            smm2[row][wn] = rm_[s]; sml2[row][wn] = rl_[s]; smt2[row][wn] = rt_[s];
            smbv2[row][wn] = rbv_[s]; smbi2[row][wn] = rbi_[s];
        }
    }
    __syncthreads();

    // ---- merge N halves, per-row finals
    if (tid < 128) {
        int row = tid;
        float m0 = smm2[row][0], m1 = smm2[row][1];
        float nm = fmaxf(m0, m1);
        float s1 = __expf(m0 - nm), s2 = __expf(m1 - nm);
        float lsum = sml2[row][0] * s1 + sml2[row][1] * s2;
        float tsum = smt2[row][0] * s1 + smt2[row][1] * s2;
        float bv = smbv2[row][0]; int bi = smbi2[row][0];
        if (smbv2[row][1] > bv || (smbv2[row][1] == bv && smbi2[row][1] < bi)) {
            bv = smbv2[row][1]; bi = smbi2[row][1];
        }
        float palog = tsum / lsum;
        float lse = nm + logf(lsum);
        redk[row] = palog - lse;        // sum p*logp
        redc[row] = halfC - palog;      // -(sum p*logit)
        finbi[row] = bi;
    }
    __syncthreads();
    for (int s = 64; s > 0; s >>= 1) {
        if (tid < s) { redk[tid] += redk[tid + s]; redc[tid] += redc[tid + s]; }
        __syncthreads();
    }
    if (tid == 0) {
        g_part[blockIdx.x][0] = redk[0];
        g_part[blockIdx.x][1] = redc[0];
    }

    // ---- gather z_quantized = embedding[argmax]
    {
        const int rr = tid >> 1;
        const int hh = tid & 1;
        const int bi = finbi[rr];
        const float4* src = (const float4*)(emb + (size_t)bi * EDIM) + hh * 16;
        float4* dst = (float4*)(out + (size_t)(block_row + rr) * EDIM) + hh * 16;
        #pragma unroll
        for (int i = 0; i < 16; i++) dst[i] = src[i];
    }
}

// ---------------------------------------------------------------------------
__global__ void gsq_finish_kernel(float* __restrict__ out, int n, int nblocks) {
    __shared__ double sk[256], sc[256];
    int t = threadIdx.x;
    double a = 0.0, b = 0.0;
    for (int i = t; i < nblocks; i += 256) {
        a += (double)g_part[i][0];
        b += (double)g_part[i][1];
    }
    sk[t] = a; sc[t] = b;
    __syncthreads();
    for (int s = 128; s > 0; s >>= 1) {
        if (t < s) { sk[t] += sk[t + s]; sc[t] += sc[t + s]; }
        __syncthreads();
    }
    if (t == 0) {
        double dn = (double)n;
        out[(size_t)n * EDIM + 0] = (float)(sk[0] / dn);
        out[(size_t)n * EDIM + 1] = (float)(sc[0] / dn);
    }
}

// ---------------------------------------------------------------------------
extern "C" void kernel_launch(void* const* d_in, const int* in_sizes, int n_in,
                              void* d_out, int out_size) {
    const float* z   = (const float*)d_in[0];
    const float* emb = (const float*)d_in[1];
    const float* vql = (const float*)d_in[2];
    const float* vi  = (const float*)d_in[3];
    float* out = (float*)d_out;

    int n  = in_sizes[0] / EDIM;
    int ne = in_sizes[1] / EDIM;

    size_t smem_bytes = 3 * 65536;     // Z + two E buffers = 192 KB
    cudaFuncSetAttribute(gsq_main_kernel,
                         cudaFuncAttributeMaxDynamicSharedMemorySize,
                         (int)smem_bytes);

    int prep_threads = 256;
    int prep_blocks = (n + ne + prep_threads - 1) / prep_threads;
    gsq_prep_kernel<<<prep_blocks, prep_threads>>>(z, emb, vql, vi, n, ne);

    gsq_main_kernel<<<n / BM, NTHREADS, smem_bytes>>>(z, emb, out, n, ne);

    gsq_finish_kernel<<<1, 256>>>(out, n, n / BM);
}

// round 8
// speedup vs baseline: 3.1272x; 1.7412x over previous
#include <cuda_runtime.h>
#include <cuda_fp16.h>
#include <math.h>
#include <stdint.h>

#define EDIM 128
#define BM 128
#define BN 128
#define NTHREADS 256
#define F_LOG2PI 1.8378770664093453f

__device__ float g_z2[65536];
__device__ float g_e2[4096];
__device__ float g_scal[2];          // [0]=1/v  [1]=0.5*EDIM*(log v + LOG2PI)
__device__ float g_part[512][2];

// SMEM map (dynamic, 192KB):
//   [0,32K)    Z_hi fp16 [128][128]
//   [32K,64K)  Z_lo
//   [64K,96K)  E0_hi    [96K,128K)  E0_lo
//   [128K,160K) E1_hi   [160K,192K) E1_lo
#define ZH_OFF 0u
#define ZL_OFF 32768u
#define EBUF_OFF 65536u
#define EBUF_STRIDE 65536u
#define ELO_OFF 32768u

// ---------------------------------------------------------------------------
__device__ __forceinline__ uint32_t smem_u32(const void* p) {
    uint32_t a;
    asm("{ .reg .u64 t; cvta.to.shared.u64 t, %1; cvt.u32.u64 %0, t; }" : "=r"(a) : "l"(p));
    return a;
}

#define LDMX4(r0, r1, r2, r3, addr)                                            \
    asm volatile("ldmatrix.sync.aligned.m8n8.x4.shared.b16 {%0,%1,%2,%3}, [%4];" \
        : "=r"(r0), "=r"(r1), "=r"(r2), "=r"(r3) : "r"(addr))

#define MMA_F16(c, a, b)                                                       \
    asm volatile("mma.sync.aligned.m16n8k16.row.col.f32.f16.f16.f32 "          \
        "{%0,%1,%2,%3},{%4,%5,%6,%7},{%8,%9},{%0,%1,%2,%3};"                   \
        : "+f"((c)[0]), "+f"((c)[1]), "+f"((c)[2]), "+f"((c)[3])               \
        : "r"((a)[0]), "r"((a)[1]), "r"((a)[2]), "r"((a)[3]),                  \
          "r"((b)[0]), "r"((b)[1]))

// fp16 tile [128 rows][128 cols], 256B rows, 16B-chunk XOR swizzle
__device__ __forceinline__ uint32_t tswoff(int row, int chunk) {
    return (uint32_t)((row << 8) + (((chunk ^ (row & 7))) << 4));
}

// ---------------------------------------------------------------------------
__global__ void gsq_prep_kernel(const float* __restrict__ z,
                                const float* __restrict__ emb,
                                const float* __restrict__ var_q_logit,
                                const float* __restrict__ var_init,
                                int n, int ne) {
    int t = blockIdx.x * blockDim.x + threadIdx.x;
    if (t == 0) {
        float lg = var_q_logit[0];
        float v = (1.0f / (1.0f + expf(-lg))) * 2.0f * var_init[0];
        g_scal[0] = 1.0f / v;
        g_scal[1] = 0.5f * (float)EDIM * (logf(v) + F_LOG2PI);
    }
    if (t < n) {
        const float4* p = (const float4*)(z + (size_t)t * EDIM);
        float s = 0.0f;
        #pragma unroll
        for (int i = 0; i < EDIM / 4; i++) {
            float4 v4 = p[i];
            s += v4.x * v4.x + v4.y * v4.y + v4.z * v4.z + v4.w * v4.w;
        }
        g_z2[t] = s;
    } else if (t < n + ne) {
        int k = t - n;
        const float4* p = (const float4*)(emb + (size_t)k * EDIM);
        float s = 0.0f;
        #pragma unroll
        for (int i = 0; i < EDIM / 4; i++) {
            float4 v4 = p[i];
            s += v4.x * v4.x + v4.y * v4.y + v4.z * v4.z + v4.w * v4.w;
        }
        g_e2[k] = s;
    }
}

// ---------------------------------------------------------------------------
// split-load one [128][128] fp32 tile from gmem into (hi, lo) fp16 SMEM tiles
// ---------------------------------------------------------------------------
__device__ __forceinline__ void split_tile(const float* __restrict__ src,
                                           char* dst_hi, char* dst_lo, int tid) {
    #pragma unroll
    for (int i = 0; i < 8; i++) {
        int u = i * NTHREADS + tid;         // 0..2047 16B-chunks
        int row = u >> 4, chunk = u & 15;
        const float4* s4 = (const float4*)(src + (size_t)row * 128 + chunk * 8);
        float4 va = s4[0], vb = s4[1];
        __half2 h0 = __floats2half2_rn(va.x, va.y);
        __half2 h1 = __floats2half2_rn(va.z, va.w);
        __half2 h2 = __floats2half2_rn(vb.x, vb.y);
        __half2 h3 = __floats2half2_rn(vb.z, vb.w);
        float2 f0 = __half22float2(h0), f1 = __half22float2(h1);
        float2 f2 = __half22float2(h2), f3 = __half22float2(h3);
        __half2 l0 = __floats2half2_rn(va.x - f0.x, va.y - f0.y);
        __half2 l1 = __floats2half2_rn(va.z - f1.x, va.w - f1.y);
        __half2 l2 = __floats2half2_rn(vb.x - f2.x, vb.y - f2.y);
        __half2 l3 = __floats2half2_rn(vb.z - f3.x, vb.w - f3.y);
        uint32_t off = tswoff(row, chunk);
        uint4 ph, pl;
        ph.x = *(uint32_t*)&h0; ph.y = *(uint32_t*)&h1;
        ph.z = *(uint32_t*)&h2; ph.w = *(uint32_t*)&h3;
        pl.x = *(uint32_t*)&l0; pl.y = *(uint32_t*)&l1;
        pl.z = *(uint32_t*)&l2; pl.w = *(uint32_t*)&l3;
        *(uint4*)(dst_hi + off) = ph;
        *(uint4*)(dst_lo + off) = pl;
    }
}

// ---------------------------------------------------------------------------
// Main: m16n8k16 fp16 3-split GEMM fused with online softmax + argmax.
// 8 warps = 4(M) x 2(N); warp tile 32x64; hi/lo fp16 presplit in SMEM.
// ---------------------------------------------------------------------------
__global__ __launch_bounds__(NTHREADS, 1)
void gsq_main_kernel(const float* __restrict__ z,
                     const float* __restrict__ emb,
                     float* __restrict__ out,
                     int n, int ne) {
    extern __shared__ char dynsm[];
    __shared__ float e2v_s[4096];
    __shared__ float smm2[128][2], sml2[128][2], smt2[128][2], smbv2[128][2];
    __shared__ int   smbi2[128][2];
    __shared__ float redk[128], redc[128];
    __shared__ int   finbi[128];

    const int tid  = threadIdx.x;
    const int w    = tid >> 5;
    const int l    = tid & 31;
    const int wm   = w >> 1;            // 0..3  M band
    const int wn   = w & 1;             // 0..1  N half
    const int block_row = blockIdx.x * BM;

    const uint32_t sb32 = smem_u32(dynsm);

    const float inv_v = g_scal[0];
    const float halfC = g_scal[1];

    for (int i = tid; i < 4096; i += NTHREADS) e2v_s[i] = 0.5f * inv_v * g_e2[i];

    // per-thread row constants (s = mb*2+half -> row = wm*32 + mb*16 + l/4 + half*8)
    float c_r[4];
    #pragma unroll
    for (int s = 0; s < 4; s++) {
        int row = wm * 32 + (s >> 1) * 16 + (l >> 2) + (s & 1) * 8;
        c_r[s] = -0.5f * inv_v * g_z2[block_row + row];
    }

    // ---- split Z into resident hi/lo tiles; prefill E tile 0
    split_tile(z + (size_t)block_row * EDIM, dynsm + ZH_OFF, dynsm + ZL_OFF, tid);
    split_tile(emb, dynsm + EBUF_OFF, dynsm + EBUF_OFF + ELO_OFF, tid);

    // ldmatrix per-lane address components
    const int lj = l >> 3;              // matrix index 0..3
    const int li = l & 7;               // row within matrix
    // A: j&1 -> row block (+8), j>>1 -> k chunk (+1)
    const int a_row_base = wm * 32 + ((lj & 1) << 3) + li;   // + mb*16
    const int a_kchunk   = lj >> 1;                          // + kb*2
    // B: j>>1 -> row block (+8), j&1 -> k chunk (+1)
    const int b_row_base = wn * 64 + ((lj >> 1) << 3) + li;  // + q*16
    const int b_kchunk   = lj & 1;                           // + kb*2

    // running per-row softmax state (4 rows per thread; quad-redundant)
    float rm_[4], rl_[4], rt_[4], rbv_[4];
    int rbi_[4];
    #pragma unroll
    for (int s = 0; s < 4; s++) { rm_[s] = -INFINITY; rl_[s] = 0.f; rt_[s] = 0.f; rbv_[s] = -INFINITY; rbi_[s] = 0; }

    const int ntiles = ne / BN;         // 32
    for (int t = 0; t < ntiles; t++) {
        __syncthreads();                // E buf (t&1) ready; buf ((t+1)&1) free

        const uint32_t eh32 = sb32 + EBUF_OFF + (uint32_t)(t & 1) * EBUF_STRIDE;
        const uint32_t el32 = eh32 + ELO_OFF;
        const uint32_t zh32 = sb32 + ZH_OFF;
        const uint32_t zl32 = sb32 + ZL_OFF;

        // ---- GEMM: 3-split fp16, warp tile 32x64
        float acc[2][8][4];
        #pragma unroll
        for (int mb = 0; mb < 2; mb++)
            #pragma unroll
            for (int nb = 0; nb < 8; nb++)
                #pragma unroll
                for (int q = 0; q < 4; q++) acc[mb][nb][q] = 0.0f;

        #pragma unroll
        for (int kb = 0; kb < 8; kb++) {
            uint32_t Ah[2][4], Al[2][4];
            #pragma unroll
            for (int mb = 0; mb < 2; mb++) {
                int arow = a_row_base + mb * 16;
                uint32_t aoff = tswoff(arow, kb * 2 + a_kchunk);
                LDMX4(Ah[mb][0], Ah[mb][1], Ah[mb][2], Ah[mb][3], zh32 + aoff);
                LDMX4(Al[mb][0], Al[mb][1], Al[mb][2], Al[mb][3], zl32 + aoff);
            }
            uint32_t Bh[8][2], Bl[8][2];
            #pragma unroll
            for (int q = 0; q < 4; q++) {
                int brow = b_row_base + q * 16;
                uint32_t boff = tswoff(brow, kb * 2 + b_kchunk);
                LDMX4(Bh[2*q][0], Bh[2*q][1], Bh[2*q+1][0], Bh[2*q+1][1], eh32 + boff);
                LDMX4(Bl[2*q][0], Bl[2*q][1], Bl[2*q+1][0], Bl[2*q+1][1], el32 + boff);
            }
            #pragma unroll
            for (int mb = 0; mb < 2; mb++)
                #pragma unroll
                for (int nb = 0; nb < 8; nb++) {
                    MMA_F16(acc[mb][nb], Ah[mb], Bh[nb]);   // hi*hi
                    MMA_F16(acc[mb][nb], Ah[mb], Bl[nb]);   // hi*lo
                    MMA_F16(acc[mb][nb], Al[mb], Bh[nb]);   // lo*hi
                }
        }

        // ---- producer: split next E tile into the other buffer
        if (t + 1 < ntiles) {
            char* dh = dynsm + EBUF_OFF + (size_t)((t + 1) & 1) * EBUF_STRIDE;
            split_tile(emb + (size_t)(t + 1) * BN * EDIM, dh, dh + ELO_OFF, tid);
        }

        // ---- fused epilogue: online softmax stats per row
        const int colq = (l & 3) * 2;
        #pragma unroll
        for (int mb = 0; mb < 2; mb++) {
            #pragma unroll
            for (int half = 0; half < 2; half++) {
                const int s = mb * 2 + half;
                float vals[16];
                int cb0 = t * BN + wn * 64;
                #pragma unroll
                for (int nb = 0; nb < 8; nb++) {
                    #pragma unroll
                    for (int j = 0; j < 2; j++) {
                        int col = cb0 + nb * 8 + colq + j;
                        vals[nb * 2 + j] =
                            fmaf(acc[mb][nb][half * 2 + j], inv_v, c_r[s]) - e2v_s[col];
                    }
                }
                float vmax = vals[0];
                int vidx = cb0 + colq;
                #pragma unroll
                for (int q = 1; q < 16; q++) {
                    int col = cb0 + (q >> 1) * 8 + colq + (q & 1);
                    if (vals[q] > vmax) { vmax = vals[q]; vidx = col; }
                }
                #pragma unroll
                for (int off = 1; off < 4; off <<= 1) {
                    float ov = __shfl_xor_sync(0xffffffffu, vmax, off);
                    int   oi = __shfl_xor_sync(0xffffffffu, vidx, off);
                    if (ov > vmax || (ov == vmax && oi < vidx)) { vmax = ov; vidx = oi; }
                }
                float ls = 0.0f, ts = 0.0f;
                #pragma unroll
                for (int q = 0; q < 16; q++) {
                    float e = __expf(vals[q] - vmax);
                    ls += e;
                    ts = fmaf(vals[q], e, ts);
                }
                #pragma unroll
                for (int off = 1; off < 4; off <<= 1) {
                    ls += __shfl_xor_sync(0xffffffffu, ls, off);
                    ts += __shfl_xor_sync(0xffffffffu, ts, off);
                }
                float nm = fmaxf(rm_[s], vmax);
                float s1 = __expf(rm_[s] - nm), s2 = __expf(vmax - nm);
                rl_[s] = rl_[s] * s1 + ls * s2;
                rt_[s] = rt_[s] * s1 + ts * s2;
                rm_[s] = nm;
                if (vmax > rbv_[s]) { rbv_[s] = vmax; rbi_[s] = vidx; }
            }
        }
    }

    // ---- publish per-(row, wn) states
    __syncthreads();
    if ((l & 3) == 0) {
        #pragma unroll
        for (int s = 0; s < 4; s++) {
            int row = wm * 32 + (s >> 1) * 16 + (l >> 2) + (s & 1) * 8;
            smm2[row][wn] = rm_[s]; sml2[row][wn] = rl_[s]; smt2[row][wn] = rt_[s];
            smbv2[row][wn] = rbv_[s]; smbi2[row][wn] = rbi_[s];
        }
    }
    __syncthreads();

    // ---- merge N halves, per-row finals
    if (tid < 128) {
        int row = tid;
        float m0 = smm2[row][0], m1 = smm2[row][1];
        float nm = fmaxf(m0, m1);
        float s1 = __expf(m0 - nm), s2 = __expf(m1 - nm);
        float lsum = sml2[row][0] * s1 + sml2[row][1] * s2;
        float tsum = smt2[row][0] * s1 + smt2[row][1] * s2;
        float bv = smbv2[row][0]; int bi = smbi2[row][0];
        if (smbv2[row][1] > bv || (smbv2[row][1] == bv && smbi2[row][1] < bi)) {
            bv = smbv2[row][1]; bi = smbi2[row][1];
        }
        float palog = tsum / lsum;
        float lse = nm + logf(lsum);
        redk[row] = palog - lse;        // sum p*logp
        redc[row] = halfC - palog;      // -(sum p*logit)
        finbi[row] = bi;
    }
    __syncthreads();
    for (int s = 64; s > 0; s >>= 1) {
        if (tid < s) { redk[tid] += redk[tid + s]; redc[tid] += redc[tid + s]; }
        __syncthreads();
    }
    if (tid == 0) {
        g_part[blockIdx.x][0] = redk[0];
        g_part[blockIdx.x][1] = redc[0];
    }

    // ---- gather z_quantized = embedding[argmax]
    {
        const int rr = tid >> 1;
        const int hh = tid & 1;
        const int bi = finbi[rr];
        const float4* src = (const float4*)(emb + (size_t)bi * EDIM) + hh * 16;
        float4* dst = (float4*)(out + (size_t)(block_row + rr) * EDIM) + hh * 16;
        #pragma unroll
        for (int i = 0; i < 16; i++) dst[i] = src[i];
    }
}

// ---------------------------------------------------------------------------
__global__ void gsq_finish_kernel(float* __restrict__ out, int n, int nblocks) {
    __shared__ double sk[256], sc[256];
    int t = threadIdx.x;
    double a = 0.0, b = 0.0;
    for (int i = t; i < nblocks; i += 256) {
        a += (double)g_part[i][0];
        b += (double)g_part[i][1];
    }
    sk[t] = a; sc[t] = b;
    __syncthreads();
    for (int s = 128; s > 0; s >>= 1) {
        if (t < s) { sk[t] += sk[t + s]; sc[t] += sc[t + s]; }
        __syncthreads();
    }
    if (t == 0) {
        double dn = (double)n;
        out[(size_t)n * EDIM + 0] = (float)(sk[0] / dn);
        out[(size_t)n * EDIM + 1] = (float)(sc[0] / dn);
    }
}

// ---------------------------------------------------------------------------
extern "C" void kernel_launch(void* const* d_in, const int* in_sizes, int n_in,
                              void* d_out, int out_size) {
    const float* z   = (const float*)d_in[0];
    const float* emb = (const float*)d_in[1];
    const float* vql = (const float*)d_in[2];
    const float* vi  = (const float*)d_in[3];
    float* out = (float*)d_out;

    int n  = in_sizes[0] / EDIM;
    int ne = in_sizes[1] / EDIM;

    size_t smem_bytes = 192 * 1024;    // Zhi/Zlo + 2 x (Ehi+Elo)
    cudaFuncSetAttribute(gsq_main_kernel,
                         cudaFuncAttributeMaxDynamicSharedMemorySize,
                         (int)smem_bytes);

    int prep_threads = 256;
    int prep_blocks = (n + ne + prep_threads - 1) / prep_threads;
    gsq_prep_kernel<<<prep_blocks, prep_threads>>>(z, emb, vql, vi, n, ne);

    gsq_main_kernel<<<n / BM, NTHREADS, smem_bytes>>>(z, emb, out, n, ne);

    gsq_finish_kernel<<<1, 256>>>(out, n, n / BM);
}